// round 15
// baseline (speedup 1.0000x reference)
#include <cuda_runtime.h>
#include <cuda_fp16.h>
#include <math.h>

#define NB   8
#define NC   256
#define NH   128
#define NW   128
#define NHW  16384
#define NMID 64
#define NANG 4
#define GRPPIX 64
#define NGRP (NHW / GRPPIX)    // 256 pixel-groups per image
#define NRED 8                 // second-stage partials per (a,b)
#define WEPS 1e-5f

// ---------------- scratch (static __device__, no allocations) ----------------
__device__ __half g_xh[(size_t)NB * NHW * NC];     // 67 MB  x in NHWC fp16
__device__ float g_trig[2 * NANG];
__device__ float g_A4[NHW * 4];                    // per-pixel A weights, 4 angles packed
__device__ float g_mpart[(size_t)NANG * NB * NGRP * NC];
__device__ float g_mpart2[(size_t)NANG * NB * NRED * NC];
__device__ float g_ca[NANG * NB * NC];
__device__ float g_avg[(size_t)NANG * NB * NHW];
__device__ float g_maxm[(size_t)NANG * NB * NHW];
__device__ float g_sa[(size_t)NANG * NB * NHW];
// precomputed geometry (batch-invariant)
__device__ int4   g_gidx[NANG * NHW];              // fwd gather corner pixel idx (-1 = skip)
__device__ float4 g_gw[NANG * NHW];                // fwd gather corner weights
__device__ float4 g_T[(size_t)NANG * NHW * 16];    // fused: per-cell 4-corner tent weights
__device__ int4   g_pinv[NANG * NHW];              // fused: inverse-corner sa indices
__device__ int    g_anchor[NANG * NHW];            // (bx+8) | (by+8)<<8 | validmask<<16

// ---------------- helpers ----------------
__device__ __forceinline__ float ncoord(int j) { return -1.0f + (float)j * (2.0f / 127.0f); }
__device__ __forceinline__ float ncoordf(float j) { return -1.0f + j * (2.0f / 127.0f); }
__device__ __forceinline__ float sigm(float v) { return 1.0f / (1.0f + expf(-v)); }

// Accumulate w * 8 fp16 channels (one uint4 row chunk) into fp32 acc[8].
__device__ __forceinline__ void acc_row8(float* acc, float w, const uint4 h) {
    const __half2* hp = (const __half2*)&h;
#pragma unroll
    for (int i = 0; i < 4; i++) {
        float2 f = __half22float2(hp[i]);
        acc[2 * i]     = fmaf(w, f.x, acc[2 * i]);
        acc[2 * i + 1] = fmaf(w, f.y, acc[2 * i + 1]);
    }
}

// ---------------- kernels ----------------

// Pure NCHW -> NHWC(fp16) transpose (64-channel tiles, half2 stores).
__global__ void k_transpose(const float* __restrict__ x) {
    __shared__ float s[64][33];
    int b = blockIdx.z, c0 = blockIdx.y * 64, p0 = blockIdx.x * 32;
    int tx = threadIdx.x, ty = threadIdx.y;
    s[ty][tx]      = x[((size_t)(b * NC + c0 + ty)) * NHW + p0 + tx];
    s[ty + 32][tx] = x[((size_t)(b * NC + c0 + 32 + ty)) * NHW + p0 + tx];
    __syncthreads();
    __half2 h2 = __floats2half2_rn(s[2 * tx][ty], s[2 * tx + 1][ty]);
    *(__half2*)(g_xh + ((size_t)b * NHW + p0 + ty) * NC + c0 + 2 * tx) = h2;
}

// A map + batch-invariant geometry precompute; one thread per (angle, pixel).
__global__ void k_Amap(const float* __restrict__ angles) {
    int id = blockIdx.x * 256 + threadIdx.x;
    int a = id >> 14, p = id & (NHW - 1);
    float ang = angles[a];
    float c_ = cosf(ang), s_ = sinf(ang);
    if (blockIdx.x == 0 && threadIdx.x < NANG) {
        float aa = angles[threadIdx.x];
        g_trig[2 * threadIdx.x]     = cosf(aa);
        g_trig[2 * threadIdx.x + 1] = sinf(aa);
    }
    int sy = p >> 7, sx = p & 127;

    // ---- A map (source-pixel weight accumulation), packed per-pixel float4 ----
    {
        float dx = (float)sx - 63.5f, dy = (float)sy - 63.5f;
        float pxf = c_ * dx + s_ * dy + 63.5f;
        float pyf = -s_ * dx + c_ * dy + 63.5f;
        int px0 = (int)floorf(pxf + 0.5f) - 2;
        int py0 = (int)floorf(pyf + 0.5f) - 2;
        float acc = 0.f;
        for (int py = py0; py < py0 + 5; py++) {
            for (int px = px0; px < px0 + 5; px++) {
                if ((unsigned)px < 128u && (unsigned)py < 128u) {
                    float X = ncoord(px), Y = ncoord(py);
                    float gx = c_ * X - s_ * Y, gy = s_ * X + c_ * Y;
                    float ix = (gx + 1.0f) * 63.5f, iy = (gy + 1.0f) * 63.5f;
                    float tx = 1.0f - fabsf(ix - (float)sx);
                    float ty = 1.0f - fabsf(iy - (float)sy);
                    if (tx > 0.f && ty > 0.f) acc += tx * ty;
                }
            }
        }
        g_A4[p * 4 + a] = acc * (1.0f / (float)NHW);
    }

    float X = ncoord(sx), Y = ncoord(sy);

    // ---- forward-gather corner geometry (for k_avgmax) ----
    {
        float gx = c_ * X - s_ * Y, gy = s_ * X + c_ * Y;
        float fix = (gx + 1.0f) * 63.5f, fiy = (gy + 1.0f) * 63.5f;
        float fx0 = floorf(fix), fy0 = floorf(fiy);
        float wx1 = fix - fx0, wx0 = 1.0f - wx1;
        float wy1 = fiy - fy0, wy0 = 1.0f - wy1;
        float cx[4] = {fx0, fx0 + 1.0f, fx0,        fx0 + 1.0f};
        float cy[4] = {fy0, fy0,        fy0 + 1.0f, fy0 + 1.0f};
        float cw[4] = {wx0 * wy0, wx1 * wy0, wx0 * wy1, wx1 * wy1};
        int gi[4]; float gw[4];
#pragma unroll
        for (int k = 0; k < 4; k++) {
            bool ok = (cx[k] >= 0.f && cx[k] <= 127.f && cy[k] >= 0.f &&
                       cy[k] <= 127.f && cw[k] > WEPS);
            gi[k] = ok ? ((int)cy[k] * NW + (int)cx[k]) : -1;
            gw[k] = cw[k];
        }
        g_gidx[id] = make_int4(gi[0], gi[1], gi[2], gi[3]);
        g_gw[id]   = make_float4(gw[0], gw[1], gw[2], gw[3]);
    }

    // ---- inverse-pass cell-weight matrix + valid mask (for k_fused) ----
    {
        float gx = c_ * X + s_ * Y, gy = -s_ * X + c_ * Y;   // inverse grid
        float ixv = (gx + 1.0f) * 63.5f, iyv = (gy + 1.0f) * 63.5f;
        float x0 = floorf(ixv), y0 = floorf(iyv);
        float wx1 = ixv - x0, wx0 = 1.0f - wx1;
        float wy1 = iyv - y0, wy0 = 1.0f - wy1;

        float fx[4], fy[4], wj[4];
        int pj[4];
        float minfx = 1e9f, minfy = 1e9f;
#pragma unroll
        for (int j = 0; j < 4; j++) {
            float fpx = x0 + (float)(j & 1);
            float fpy = y0 + (float)(j >> 1);
            float wi = ((j & 1) ? wx1 : wx0) * ((j >> 1) ? wy1 : wy0);
            bool ok = (fpx >= 0.f && fpx <= 127.f && fpy >= 0.f && fpy <= 127.f &&
                       wi > WEPS);
            wj[j] = ok ? wi : 0.f;
            pj[j] = ok ? ((int)fpy * NW + (int)fpx) : 0;
            if (ok) {
                float fgx = c_ * ncoordf(fpx) - s_ * ncoordf(fpy);
                float fgy = s_ * ncoordf(fpx) + c_ * ncoordf(fpy);
                fx[j] = (fgx + 1.0f) * 63.5f;
                fy[j] = (fgy + 1.0f) * 63.5f;
                minfx = fminf(minfx, fx[j]);
                minfy = fminf(minfy, fy[j]);
            } else {
                fx[j] = 1e9f; fy[j] = 1e9f;
            }
        }
        int bx = 0, by = 0;
        if (minfx < 500.f) {
            bx = (int)floorf(minfx);
            by = (int)floorf(minfy);
        }
        g_pinv[id] = make_int4(pj[0], pj[1], pj[2], pj[3]);
        float4* Trow = g_T + (size_t)id * 16;
        unsigned tmask = 0;
#pragma unroll
        for (int cell = 0; cell < 16; cell++) {
            int cxk = bx + (cell & 3), cyk = by + ((cell >> 2) & 3);
            float cellx = (float)cxk, celly = (float)cyk;
            float t[4];
            float tsum = 0.f;
#pragma unroll
            for (int j = 0; j < 4; j++) {
                float tx = fmaxf(0.f, 1.0f - fabsf(fx[j] - cellx));
                float ty = fmaxf(0.f, 1.0f - fabsf(fy[j] - celly));
                t[j] = wj[j] * tx * ty;
                tsum += t[j];
            }
            Trow[cell] = make_float4(t[0], t[1], t[2], t[3]);
            if ((unsigned)cxk < 128u && (unsigned)cyk < 128u && tsum > WEPS)
                tmask |= 1u << cell;
        }
        g_anchor[id] = (bx + 8) | ((by + 8) << 8) | ((int)tmask << 16);
    }
}

// Weighted means for all 4 angles in ONE pass over x (NHWC fp16).
// Warp per 64-pixel group; lane owns 8 channels -> NO cross-lane reduction.
__global__ void k_mean() {
    int w = blockIdx.x * 8 + (threadIdx.x >> 5);
    int lane = threadIdx.x & 31;
    int b = w >> 8;                  // NGRP = 256 groups per batch
    int grp = w & (NGRP - 1);
    const __half* xb = g_xh + ((size_t)b * NHW + grp * GRPPIX) * NC;
    const float4* A4 = (const float4*)g_A4 + grp * GRPPIX;
    float acc[4][8];
#pragma unroll
    for (int a = 0; a < 4; a++)
#pragma unroll
        for (int i = 0; i < 8; i++) acc[a][i] = 0.f;
#pragma unroll 4
    for (int p = 0; p < GRPPIX; p++) {
        uint4 row = ((const uint4*)(xb + (size_t)p * NC))[lane];
        float4 aw = A4[p];
        const __half2* hp = (const __half2*)&row;
        float f[8];
#pragma unroll
        for (int i = 0; i < 4; i++) {
            float2 v = __half22float2(hp[i]);
            f[2 * i] = v.x; f[2 * i + 1] = v.y;
        }
#pragma unroll
        for (int i = 0; i < 8; i++) {
            acc[0][i] = fmaf(aw.x, f[i], acc[0][i]);
            acc[1][i] = fmaf(aw.y, f[i], acc[1][i]);
            acc[2][i] = fmaf(aw.z, f[i], acc[2][i]);
            acc[3][i] = fmaf(aw.w, f[i], acc[3][i]);
        }
    }
#pragma unroll
    for (int a = 0; a < 4; a++)
#pragma unroll
        for (int i = 0; i < 8; i++)
            g_mpart[((size_t)((a * NB + b) * NGRP) + grp) * NC + lane * 8 + i] = acc[a][i];
}

// Stage-A reduction: 256 blocks; block (ab, part) reduces 32 group-partials.
__global__ void k_reduce() {
    int ab = blockIdx.x >> 3;
    int part = blockIdx.x & 7;
    int tid = threadIdx.x;
    const float* src = g_mpart + ((size_t)ab * NGRP + part * 32) * NC + tid;
    float s = 0.f;
#pragma unroll 8
    for (int g = 0; g < 32; g++) s += src[(size_t)g * NC];
    g_mpart2[((size_t)ab * NRED + part) * NC + tid] = s;
}

// Final 8-way reduction + channel attention MLP.
__global__ void k_chatt(const float* __restrict__ w1, const float* __restrict__ bng,
                        const float* __restrict__ bnb, const float* __restrict__ bnm,
                        const float* __restrict__ bnv, const float* __restrict__ w2) {
    __shared__ float sm[NC];
    __shared__ float sh[NMID];
    int ab = blockIdx.x;
    int tid = threadIdx.x;
    {
        const float* src = g_mpart2 + (size_t)ab * NRED * NC + tid;
        float ssum = 0.f;
#pragma unroll
        for (int g = 0; g < NRED; g++) ssum += src[(size_t)g * NC];
        sm[tid] = ssum;
    }
    __syncthreads();
    if (tid < NMID) {
        float hv = 0.f;
        const float* w1r = w1 + tid * NC;
        for (int c = 0; c < NC; c++) hv = fmaf(sm[c], w1r[c], hv);
        hv = (hv - bnm[tid]) * rsqrtf(bnv[tid] + 1e-5f) * bng[tid] + bnb[tid];
        sh[tid] = fmaxf(hv, 0.f);
    }
    __syncthreads();
    float cv = 0.f;
    const float* w2r = w2 + tid * NMID;
    for (int j = 0; j < NMID; j++) cv = fmaf(sh[j], w2r[j], cv);
    g_ca[ab * NC + tid] = sigm(cv);
}

// Channel-attended rotated stats; 2 adjacent pixels per warp (shfl reductions).
__global__ void k_avgmax() {
    int w2 = blockIdx.x * 8 + (threadIdx.x >> 5);
    int lane = threadIdx.x & 31;
    int a = w2 >> 16;
    int b = (w2 >> 13) & 7;
    int p = (w2 & 8191) * 2;
    const __half* xb = g_xh + (size_t)b * NHW * NC;
    int gid = a * NHW + p;
    int4 gi0 = g_gidx[gid], gi1 = g_gidx[gid + 1];
    float4 gw0 = g_gw[gid], gw1 = g_gw[gid + 1];
    float acc0[8], acc1[8];
#pragma unroll
    for (int i = 0; i < 8; i++) { acc0[i] = 0.f; acc1[i] = 0.f; }
    {
        int gia[4] = {gi0.x, gi0.y, gi0.z, gi0.w};
        float gwa[4] = {gw0.x, gw0.y, gw0.z, gw0.w};
#pragma unroll
        for (int k = 0; k < 4; k++)
            if (gia[k] >= 0)
                acc_row8(acc0, gwa[k], ((const uint4*)(xb + (size_t)gia[k] * NC))[lane]);
    }
    {
        int gia[4] = {gi1.x, gi1.y, gi1.z, gi1.w};
        float gwa[4] = {gw1.x, gw1.y, gw1.z, gw1.w};
#pragma unroll
        for (int k = 0; k < 4; k++)
            if (gia[k] >= 0)
                acc_row8(acc1, gwa[k], ((const uint4*)(xb + (size_t)gia[k] * NC))[lane]);
    }
    const float4* car = (const float4*)(g_ca + (size_t)(a * NB + b) * NC);
    float4 ca0 = car[lane * 2], ca1 = car[lane * 2 + 1];
    float cav[8] = {ca0.x, ca0.y, ca0.z, ca0.w, ca1.x, ca1.y, ca1.z, ca1.w};
    float sum0 = 0.f, mx0 = -1e30f, sum1 = 0.f, mx1 = -1e30f;
#pragma unroll
    for (int i = 0; i < 8; i++) {
        float u = cav[i] * acc0[i], v = cav[i] * acc1[i];
        sum0 += u; mx0 = fmaxf(mx0, u);
        sum1 += v; mx1 = fmaxf(mx1, v);
    }
#pragma unroll
    for (int o = 16; o; o >>= 1) {
        sum0 += __shfl_xor_sync(0xffffffffu, sum0, o);
        mx0 = fmaxf(mx0, __shfl_xor_sync(0xffffffffu, mx0, o));
        sum1 += __shfl_xor_sync(0xffffffffu, sum1, o);
        mx1 = fmaxf(mx1, __shfl_xor_sync(0xffffffffu, mx1, o));
    }
    if (lane == 0) {
        size_t base = (size_t)(a * NB + b) * NHW + p;
        g_avg[base]     = sum0 * (1.0f / (float)NC);
        g_avg[base + 1] = sum1 * (1.0f / (float)NC);
        g_maxm[base]     = mx0;
        g_maxm[base + 1] = mx1;
    }
}

__global__ void k_conv(const float* __restrict__ wsp) {
    __shared__ float sw[98];
    int tid = threadIdx.x;
    if (tid < 98) sw[tid] = wsp[tid];
    __syncthreads();
    int id = blockIdx.x * 256 + tid;
    int ab = id >> 14;
    int p = id & (NHW - 1);
    int py = p >> 7, px = p & 127;
    const float* av = g_avg + (size_t)ab * NHW;
    const float* mxp = g_maxm + (size_t)ab * NHW;
    float acc = 0.f;
#pragma unroll
    for (int ky = 0; ky < 7; ky++) {
        int yy = py + ky - 3;
        if ((unsigned)yy < 128u) {
#pragma unroll
            for (int kx = 0; kx < 7; kx++) {
                int xx = px + kx - 3;
                if ((unsigned)xx < 128u) {
                    int q = yy * NW + xx;
                    acc = fmaf(sw[ky * 7 + kx], av[q], acc);
                    acc = fmaf(sw[49 + ky * 7 + kx], mxp[q], acc);
                }
            }
        }
    }
    g_sa[id] = sigm(acc);
}

// Fused inverse pass, 1 warp / pixel. Axis-aligned angles merged: their
// contribution is (sum_a ca_a * sa_a[p_inv_a]) (.) x[q] -- coefficients
// accumulated per channel, ONE shared row load at the end. Diagonal angles:
// precomputed T matrices + 16-bit valid-mask walk.
__global__ void __launch_bounds__(512, 2) k_fused(float* __restrict__ out) {
    __shared__ float s[16][260];
    int b = blockIdx.x >> 10;            // 1024 16-pixel tiles per image
    int q0 = (blockIdx.x & 1023) * 16;
    int wid = threadIdx.x >> 5, lane = threadIdx.x & 31;
    int q = q0 + wid;
    float X = ncoord(q & 127), Y = ncoord(q >> 7);
    const __half* xb = g_xh + (size_t)b * NHW * NC;
    float res[8];
    float coef[8];
#pragma unroll
    for (int i = 0; i < 8; i++) { res[i] = 0.f; coef[i] = 0.f; }
    bool anyid = false;

#pragma unroll
    for (int a = 0; a < NANG; a++) {
        float c_ = g_trig[2 * a], s_ = g_trig[2 * a + 1];
        const float* saab = g_sa + (size_t)(a * NB + b) * NHW;
        const float4* car = (const float4*)(g_ca + (size_t)(a * NB + b) * NC);

        if (fabsf(s_) < 1e-4f || fabsf(c_) < 1e-4f) {
            // grid-preserving rotation: accumulate per-channel coefficient only
            anyid = true;
            float gx = c_ * X + s_ * Y, gy = -s_ * X + c_ * Y;
            int pxi = (int)((gx + 1.0f) * 63.5f + 0.5f);
            int pyi = (int)((gy + 1.0f) * 63.5f + 0.5f);
            float sav = saab[pyi * NW + pxi];
            float4 ca0 = car[lane * 2], ca1 = car[lane * 2 + 1];
            coef[0] = fmaf(ca0.x, sav, coef[0]); coef[1] = fmaf(ca0.y, sav, coef[1]);
            coef[2] = fmaf(ca0.z, sav, coef[2]); coef[3] = fmaf(ca0.w, sav, coef[3]);
            coef[4] = fmaf(ca1.x, sav, coef[4]); coef[5] = fmaf(ca1.y, sav, coef[5]);
            coef[6] = fmaf(ca1.z, sav, coef[6]); coef[7] = fmaf(ca1.w, sav, coef[7]);
        } else {
            int gid = a * NHW + q;
            int anch = g_anchor[gid];
            int bx = (anch & 255) - 8, by = ((anch >> 8) & 255) - 8;
            int4 pj = g_pinv[gid];
            float4 T = g_T[(size_t)gid * 16 + (lane & 15)];
            float wc = T.x * saab[pj.x] + T.y * saab[pj.y] +
                       T.z * saab[pj.z] + T.w * saab[pj.w];
            unsigned mask = (((unsigned)anch) >> 16) &
                            __ballot_sync(0xffffffffu, wc > WEPS);
            float t[8];
#pragma unroll
            for (int i = 0; i < 8; i++) t[i] = 0.f;
            while (mask) {
                int k = __ffs(mask) - 1;
                mask &= mask - 1;
                float w = __shfl_sync(0xffffffffu, wc, k);
                const uint4* row = (const uint4*)(xb +
                    ((by + (k >> 2)) * NW + bx + (k & 3)) * NC);
                acc_row8(t, w, row[lane]);
            }
            float4 ca0 = car[lane * 2], ca1 = car[lane * 2 + 1];
            res[0] = fmaf(ca0.x, t[0], res[0]); res[1] = fmaf(ca0.y, t[1], res[1]);
            res[2] = fmaf(ca0.z, t[2], res[2]); res[3] = fmaf(ca0.w, t[3], res[3]);
            res[4] = fmaf(ca1.x, t[4], res[4]); res[5] = fmaf(ca1.y, t[5], res[5]);
            res[6] = fmaf(ca1.z, t[6], res[6]); res[7] = fmaf(ca1.w, t[7], res[7]);
        }
    }

    if (anyid) {
        // single shared row load for all identity angles
        uint4 row = ((const uint4*)(xb + ((q >> 7) * NW + (q & 127)) * NC))[lane];
        const __half2* hp = (const __half2*)&row;
#pragma unroll
        for (int i = 0; i < 4; i++) {
            float2 f = __half22float2(hp[i]);
            res[2 * i]     = fmaf(coef[2 * i], f.x, res[2 * i]);
            res[2 * i + 1] = fmaf(coef[2 * i + 1], f.y, res[2 * i + 1]);
        }
    }

    // smem transpose: s[pixel][channel] -> NCHW stores with /4 folded in
    *(float4*)&s[wid][lane * 8]     = make_float4(res[0], res[1], res[2], res[3]);
    *(float4*)&s[wid][lane * 8 + 4] = make_float4(res[4], res[5], res[6], res[7]);
    __syncthreads();
    int pix = lane & 15, hl = lane >> 4;
#pragma unroll
    for (int it = 0; it < 8; it++) {
        int c = wid * 16 + hl * 8 + it;
        float v = s[pix][c];
        out[((size_t)(b * NC + c)) * NHW + q0 + pix] = v * 0.25f;
    }
}

// ---------------- launch ----------------
extern "C" void kernel_launch(void* const* d_in, const int* in_sizes, int n_in,
                              void* d_out, int out_size) {
    const float* x      = (const float*)d_in[0];
    const float* angles = (const float*)d_in[1];
    const float* w1     = (const float*)d_in[2];
    const float* bng    = (const float*)d_in[3];
    const float* bnb    = (const float*)d_in[4];
    const float* bnm    = (const float*)d_in[5];
    const float* bnv    = (const float*)d_in[6];
    const float* w2     = (const float*)d_in[7];
    const float* wsp    = (const float*)d_in[8];
    float* out = (float*)d_out;

    dim3 tb(32, 32);
    k_transpose<<<dim3(NHW / 32, NC / 64, NB), tb>>>(x);
    k_Amap<<<(NANG * NHW) / 256, 256>>>(angles);
    k_mean<<<NB * NGRP / 8, 256>>>();
    k_reduce<<<NANG * NB * NRED, 256>>>();
    k_chatt<<<NANG * NB, 256>>>(w1, bng, bnb, bnm, bnv, w2);
    k_avgmax<<<(NANG * NB * NHW / 2) / 8, 256>>>();
    k_conv<<<(NANG * NB * NHW) / 256, 256>>>(wsp);
    k_fused<<<NB * NHW / 16, 512>>>(out);
}

// round 16
// speedup vs baseline: 1.0559x; 1.0559x over previous
#include <cuda_runtime.h>
#include <cuda_fp16.h>
#include <math.h>

#define NB   8
#define NC   256
#define NH   128
#define NW   128
#define NHW  16384
#define NMID 64
#define NANG 4
#define GRPPIX 64
#define NGRP (NHW / GRPPIX)    // 256 pixel-groups per image
#define NRED 8                 // second-stage partials per (a,b)
#define WEPS 1e-5f

// ---------------- scratch (static __device__, no allocations) ----------------
__device__ __half g_xh[(size_t)NB * NHW * NC];     // 67 MB  x in NHWC fp16
__device__ float g_trig[2 * NANG];
__device__ float g_A4[NHW * 4];                    // per-pixel A weights, 4 angles packed
__device__ float g_mpart[(size_t)NANG * NB * NGRP * NC];
__device__ float g_mpart2[(size_t)NANG * NB * NRED * NC];
__device__ float g_ca[NANG * NB * NC];
__device__ float g_avg[(size_t)NANG * NB * NHW];
__device__ float g_maxm[(size_t)NANG * NB * NHW];
__device__ float g_sa[(size_t)NANG * NB * NHW];
// precomputed geometry (batch-invariant)
__device__ int4   g_gidx[NANG * NHW];              // fwd gather corner pixel idx (-1 = skip)
__device__ float4 g_gw[NANG * NHW];                // fwd gather corner weights
__device__ float4 g_T[(size_t)NANG * NHW * 16];    // fused: per-cell 4-corner tent weights
__device__ int4   g_pinv[NANG * NHW];              // fused: inverse-corner sa indices
__device__ int    g_anchor[NANG * NHW];            // diag: (bx+8)|(by+8)<<8|mask<<16 ; ident: p_inv idx

// ---------------- helpers ----------------
__device__ __forceinline__ float ncoord(int j) { return -1.0f + (float)j * (2.0f / 127.0f); }
__device__ __forceinline__ float ncoordf(float j) { return -1.0f + j * (2.0f / 127.0f); }
__device__ __forceinline__ float sigm(float v) { return 1.0f / (1.0f + expf(-v)); }

// Accumulate w * 8 fp16 channels (one uint4 row chunk) into fp32 acc[8].
__device__ __forceinline__ void acc_row8(float* acc, float w, const uint4 h) {
    const __half2* hp = (const __half2*)&h;
#pragma unroll
    for (int i = 0; i < 4; i++) {
        float2 f = __half22float2(hp[i]);
        acc[2 * i]     = fmaf(w, f.x, acc[2 * i]);
        acc[2 * i + 1] = fmaf(w, f.y, acc[2 * i + 1]);
    }
}

// ---------------- kernels ----------------

// Pure NCHW -> NHWC(fp16) transpose (64-channel tiles, half2 stores).
__global__ void k_transpose(const float* __restrict__ x) {
    __shared__ float s[64][33];
    int b = blockIdx.z, c0 = blockIdx.y * 64, p0 = blockIdx.x * 32;
    int tx = threadIdx.x, ty = threadIdx.y;
    s[ty][tx]      = x[((size_t)(b * NC + c0 + ty)) * NHW + p0 + tx];
    s[ty + 32][tx] = x[((size_t)(b * NC + c0 + 32 + ty)) * NHW + p0 + tx];
    __syncthreads();
    __half2 h2 = __floats2half2_rn(s[2 * tx][ty], s[2 * tx + 1][ty]);
    *(__half2*)(g_xh + ((size_t)b * NHW + p0 + ty) * NC + c0 + 2 * tx) = h2;
}

// A map + batch-invariant geometry precompute; one thread per (angle, pixel).
__global__ void k_Amap(const float* __restrict__ angles) {
    int id = blockIdx.x * 256 + threadIdx.x;
    int a = id >> 14, p = id & (NHW - 1);
    float ang = angles[a];
    float c_ = cosf(ang), s_ = sinf(ang);
    if (blockIdx.x == 0 && threadIdx.x < NANG) {
        float aa = angles[threadIdx.x];
        g_trig[2 * threadIdx.x]     = cosf(aa);
        g_trig[2 * threadIdx.x + 1] = sinf(aa);
    }
    int sy = p >> 7, sx = p & 127;

    // ---- A map (source-pixel weight accumulation), packed per-pixel float4 ----
    {
        float dx = (float)sx - 63.5f, dy = (float)sy - 63.5f;
        float pxf = c_ * dx + s_ * dy + 63.5f;
        float pyf = -s_ * dx + c_ * dy + 63.5f;
        int px0 = (int)floorf(pxf + 0.5f) - 2;
        int py0 = (int)floorf(pyf + 0.5f) - 2;
        float acc = 0.f;
        for (int py = py0; py < py0 + 5; py++) {
            for (int px = px0; px < px0 + 5; px++) {
                if ((unsigned)px < 128u && (unsigned)py < 128u) {
                    float X = ncoord(px), Y = ncoord(py);
                    float gx = c_ * X - s_ * Y, gy = s_ * X + c_ * Y;
                    float ix = (gx + 1.0f) * 63.5f, iy = (gy + 1.0f) * 63.5f;
                    float tx = 1.0f - fabsf(ix - (float)sx);
                    float ty = 1.0f - fabsf(iy - (float)sy);
                    if (tx > 0.f && ty > 0.f) acc += tx * ty;
                }
            }
        }
        g_A4[p * 4 + a] = acc * (1.0f / (float)NHW);
    }

    float X = ncoord(sx), Y = ncoord(sy);

    // ---- forward-gather corner geometry (for k_avgmax) ----
    {
        float gx = c_ * X - s_ * Y, gy = s_ * X + c_ * Y;
        float fix = (gx + 1.0f) * 63.5f, fiy = (gy + 1.0f) * 63.5f;
        float fx0 = floorf(fix), fy0 = floorf(fiy);
        float wx1 = fix - fx0, wx0 = 1.0f - wx1;
        float wy1 = fiy - fy0, wy0 = 1.0f - wy1;
        float cx[4] = {fx0, fx0 + 1.0f, fx0,        fx0 + 1.0f};
        float cy[4] = {fy0, fy0,        fy0 + 1.0f, fy0 + 1.0f};
        float cw[4] = {wx0 * wy0, wx1 * wy0, wx0 * wy1, wx1 * wy1};
        int gi[4]; float gw[4];
#pragma unroll
        for (int k = 0; k < 4; k++) {
            bool ok = (cx[k] >= 0.f && cx[k] <= 127.f && cy[k] >= 0.f &&
                       cy[k] <= 127.f && cw[k] > WEPS);
            gi[k] = ok ? ((int)cy[k] * NW + (int)cx[k]) : -1;
            gw[k] = cw[k];
        }
        g_gidx[id] = make_int4(gi[0], gi[1], gi[2], gi[3]);
        g_gw[id]   = make_float4(gw[0], gw[1], gw[2], gw[3]);
    }

    // ---- inverse-pass geometry (for k_fused) ----
    {
        float gx = c_ * X + s_ * Y, gy = -s_ * X + c_ * Y;   // inverse grid
        float ixv = (gx + 1.0f) * 63.5f, iyv = (gy + 1.0f) * 63.5f;

        if (fabsf(s_) < 1e-4f || fabsf(c_) < 1e-4f) {
            // identity (grid-preserving) angle: store only the inverse pixel index
            int pxi = (int)(ixv + 0.5f), pyi = (int)(iyv + 0.5f);
            g_anchor[id] = pyi * NW + pxi;
        } else {
            float x0 = floorf(ixv), y0 = floorf(iyv);
            float wx1 = ixv - x0, wx0 = 1.0f - wx1;
            float wy1 = iyv - y0, wy0 = 1.0f - wy1;

            float fx[4], fy[4], wj[4];
            int pj[4];
            float minfx = 1e9f, minfy = 1e9f;
#pragma unroll
            for (int j = 0; j < 4; j++) {
                float fpx = x0 + (float)(j & 1);
                float fpy = y0 + (float)(j >> 1);
                float wi = ((j & 1) ? wx1 : wx0) * ((j >> 1) ? wy1 : wy0);
                bool ok = (fpx >= 0.f && fpx <= 127.f && fpy >= 0.f && fpy <= 127.f &&
                           wi > WEPS);
                wj[j] = ok ? wi : 0.f;
                pj[j] = ok ? ((int)fpy * NW + (int)fpx) : 0;
                if (ok) {
                    float fgx = c_ * ncoordf(fpx) - s_ * ncoordf(fpy);
                    float fgy = s_ * ncoordf(fpx) + c_ * ncoordf(fpy);
                    fx[j] = (fgx + 1.0f) * 63.5f;
                    fy[j] = (fgy + 1.0f) * 63.5f;
                    minfx = fminf(minfx, fx[j]);
                    minfy = fminf(minfy, fy[j]);
                } else {
                    fx[j] = 1e9f; fy[j] = 1e9f;
                }
            }
            int bx = 0, by = 0;
            if (minfx < 500.f) {
                bx = (int)floorf(minfx);
                by = (int)floorf(minfy);
            }
            g_pinv[id] = make_int4(pj[0], pj[1], pj[2], pj[3]);
            float4* Trow = g_T + (size_t)id * 16;
            unsigned tmask = 0;
#pragma unroll
            for (int cell = 0; cell < 16; cell++) {
                int cxk = bx + (cell & 3), cyk = by + ((cell >> 2) & 3);
                float cellx = (float)cxk, celly = (float)cyk;
                float t[4];
                float tsum = 0.f;
#pragma unroll
                for (int j = 0; j < 4; j++) {
                    float tx = fmaxf(0.f, 1.0f - fabsf(fx[j] - cellx));
                    float ty = fmaxf(0.f, 1.0f - fabsf(fy[j] - celly));
                    t[j] = wj[j] * tx * ty;
                    tsum += t[j];
                }
                Trow[cell] = make_float4(t[0], t[1], t[2], t[3]);
                if ((unsigned)cxk < 128u && (unsigned)cyk < 128u && tsum > WEPS)
                    tmask |= 1u << cell;
            }
            g_anchor[id] = (bx + 8) | ((by + 8) << 8) | ((int)tmask << 16);
        }
    }
}

// Weighted means for all 4 angles in ONE pass over x (NHWC fp16).
// Warp per 64-pixel group; lane owns 8 channels -> NO cross-lane reduction.
__global__ void k_mean() {
    int w = blockIdx.x * 8 + (threadIdx.x >> 5);
    int lane = threadIdx.x & 31;
    int b = w >> 8;                  // NGRP = 256 groups per batch
    int grp = w & (NGRP - 1);
    const __half* xb = g_xh + ((size_t)b * NHW + grp * GRPPIX) * NC;
    const float4* A4 = (const float4*)g_A4 + grp * GRPPIX;
    float acc[4][8];
#pragma unroll
    for (int a = 0; a < 4; a++)
#pragma unroll
        for (int i = 0; i < 8; i++) acc[a][i] = 0.f;
#pragma unroll 4
    for (int p = 0; p < GRPPIX; p++) {
        uint4 row = ((const uint4*)(xb + (size_t)p * NC))[lane];
        float4 aw = A4[p];
        const __half2* hp = (const __half2*)&row;
        float f[8];
#pragma unroll
        for (int i = 0; i < 4; i++) {
            float2 v = __half22float2(hp[i]);
            f[2 * i] = v.x; f[2 * i + 1] = v.y;
        }
#pragma unroll
        for (int i = 0; i < 8; i++) {
            acc[0][i] = fmaf(aw.x, f[i], acc[0][i]);
            acc[1][i] = fmaf(aw.y, f[i], acc[1][i]);
            acc[2][i] = fmaf(aw.z, f[i], acc[2][i]);
            acc[3][i] = fmaf(aw.w, f[i], acc[3][i]);
        }
    }
#pragma unroll
    for (int a = 0; a < 4; a++)
#pragma unroll
        for (int i = 0; i < 8; i++)
            g_mpart[((size_t)((a * NB + b) * NGRP) + grp) * NC + lane * 8 + i] = acc[a][i];
}

// Stage-A reduction: 256 blocks; block (ab, part) reduces 32 group-partials.
__global__ void k_reduce() {
    int ab = blockIdx.x >> 3;
    int part = blockIdx.x & 7;
    int tid = threadIdx.x;
    const float* src = g_mpart + ((size_t)ab * NGRP + part * 32) * NC + tid;
    float s = 0.f;
#pragma unroll 8
    for (int g = 0; g < 32; g++) s += src[(size_t)g * NC];
    g_mpart2[((size_t)ab * NRED + part) * NC + tid] = s;
}

// Final 8-way reduction + channel attention MLP.
__global__ void k_chatt(const float* __restrict__ w1, const float* __restrict__ bng,
                        const float* __restrict__ bnb, const float* __restrict__ bnm,
                        const float* __restrict__ bnv, const float* __restrict__ w2) {
    __shared__ float sm[NC];
    __shared__ float sh[NMID];
    int ab = blockIdx.x;
    int tid = threadIdx.x;
    {
        const float* src = g_mpart2 + (size_t)ab * NRED * NC + tid;
        float ssum = 0.f;
#pragma unroll
        for (int g = 0; g < NRED; g++) ssum += src[(size_t)g * NC];
        sm[tid] = ssum;
    }
    __syncthreads();
    if (tid < NMID) {
        float hv = 0.f;
        const float* w1r = w1 + tid * NC;
        for (int c = 0; c < NC; c++) hv = fmaf(sm[c], w1r[c], hv);
        hv = (hv - bnm[tid]) * rsqrtf(bnv[tid] + 1e-5f) * bng[tid] + bnb[tid];
        sh[tid] = fmaxf(hv, 0.f);
    }
    __syncthreads();
    float cv = 0.f;
    const float* w2r = w2 + tid * NMID;
    for (int j = 0; j < NMID; j++) cv = fmaf(sh[j], w2r[j], cv);
    g_ca[ab * NC + tid] = sigm(cv);
}

// Channel-attended rotated stats; 2 adjacent pixels per warp (shfl reductions).
// launch_bounds raises occupancy floor (regs capped at 51).
__global__ void __launch_bounds__(256, 5) k_avgmax() {
    int w2 = blockIdx.x * 8 + (threadIdx.x >> 5);
    int lane = threadIdx.x & 31;
    int a = w2 >> 16;
    int b = (w2 >> 13) & 7;
    int p = (w2 & 8191) * 2;
    const __half* xb = g_xh + (size_t)b * NHW * NC;
    int gid = a * NHW + p;
    int4 gi0 = g_gidx[gid], gi1 = g_gidx[gid + 1];
    float4 gw0 = g_gw[gid], gw1 = g_gw[gid + 1];
    float acc0[8], acc1[8];
#pragma unroll
    for (int i = 0; i < 8; i++) { acc0[i] = 0.f; acc1[i] = 0.f; }
    {
        int gia[4] = {gi0.x, gi0.y, gi0.z, gi0.w};
        float gwa[4] = {gw0.x, gw0.y, gw0.z, gw0.w};
#pragma unroll
        for (int k = 0; k < 4; k++)
            if (gia[k] >= 0)
                acc_row8(acc0, gwa[k], ((const uint4*)(xb + (size_t)gia[k] * NC))[lane]);
    }
    {
        int gia[4] = {gi1.x, gi1.y, gi1.z, gi1.w};
        float gwa[4] = {gw1.x, gw1.y, gw1.z, gw1.w};
#pragma unroll
        for (int k = 0; k < 4; k++)
            if (gia[k] >= 0)
                acc_row8(acc1, gwa[k], ((const uint4*)(xb + (size_t)gia[k] * NC))[lane]);
    }
    const float4* car = (const float4*)(g_ca + (size_t)(a * NB + b) * NC);
    float4 ca0 = car[lane * 2], ca1 = car[lane * 2 + 1];
    float cav[8] = {ca0.x, ca0.y, ca0.z, ca0.w, ca1.x, ca1.y, ca1.z, ca1.w};
    float sum0 = 0.f, mx0 = -1e30f, sum1 = 0.f, mx1 = -1e30f;
#pragma unroll
    for (int i = 0; i < 8; i++) {
        float u = cav[i] * acc0[i], v = cav[i] * acc1[i];
        sum0 += u; mx0 = fmaxf(mx0, u);
        sum1 += v; mx1 = fmaxf(mx1, v);
    }
#pragma unroll
    for (int o = 16; o; o >>= 1) {
        sum0 += __shfl_xor_sync(0xffffffffu, sum0, o);
        mx0 = fmaxf(mx0, __shfl_xor_sync(0xffffffffu, mx0, o));
        sum1 += __shfl_xor_sync(0xffffffffu, sum1, o);
        mx1 = fmaxf(mx1, __shfl_xor_sync(0xffffffffu, mx1, o));
    }
    if (lane == 0) {
        size_t base = (size_t)(a * NB + b) * NHW + p;
        g_avg[base]     = sum0 * (1.0f / (float)NC);
        g_avg[base + 1] = sum1 * (1.0f / (float)NC);
        g_maxm[base]     = mx0;
        g_maxm[base + 1] = mx1;
    }
}

__global__ void k_conv(const float* __restrict__ wsp) {
    __shared__ float sw[98];
    int tid = threadIdx.x;
    if (tid < 98) sw[tid] = wsp[tid];
    __syncthreads();
    int id = blockIdx.x * 256 + tid;
    int ab = id >> 14;
    int p = id & (NHW - 1);
    int py = p >> 7, px = p & 127;
    const float* av = g_avg + (size_t)ab * NHW;
    const float* mxp = g_maxm + (size_t)ab * NHW;
    float acc = 0.f;
#pragma unroll
    for (int ky = 0; ky < 7; ky++) {
        int yy = py + ky - 3;
        if ((unsigned)yy < 128u) {
#pragma unroll
            for (int kx = 0; kx < 7; kx++) {
                int xx = px + kx - 3;
                if ((unsigned)xx < 128u) {
                    int q = yy * NW + xx;
                    acc = fmaf(sw[ky * 7 + kx], av[q], acc);
                    acc = fmaf(sw[49 + ky * 7 + kx], mxp[q], acc);
                }
            }
        }
    }
    g_sa[id] = sigm(acc);
}

// Fused inverse pass, 1 warp / pixel. Identity angles: precomputed inverse
// index in g_anchor -> one sa load + one shared row gather. Diagonal angles:
// precomputed T matrices + 16-bit valid-mask walk.
__global__ void __launch_bounds__(512, 2) k_fused(float* __restrict__ out) {
    __shared__ float s[16][260];
    int b = blockIdx.x >> 10;            // 1024 16-pixel tiles per image
    int q0 = (blockIdx.x & 1023) * 16;
    int wid = threadIdx.x >> 5, lane = threadIdx.x & 31;
    int q = q0 + wid;
    const __half* xb = g_xh + (size_t)b * NHW * NC;
    float res[8];
#pragma unroll
    for (int i = 0; i < 8; i++) res[i] = 0.f;

#pragma unroll
    for (int a = 0; a < NANG; a++) {
        float c_ = g_trig[2 * a], s_ = g_trig[2 * a + 1];
        const float* saab = g_sa + (size_t)(a * NB + b) * NHW;
        const float4* car = (const float4*)(g_ca + (size_t)(a * NB + b) * NC);

        float t[8];
#pragma unroll
        for (int i = 0; i < 8; i++) t[i] = 0.f;

        int gid = a * NHW + q;
        if (fabsf(s_) < 1e-4f || fabsf(c_) < 1e-4f) {
            // grid-preserving rotation: anchor word IS the inverse pixel index
            int pinv = g_anchor[gid];
            float sav = saab[pinv];
            const uint4* row = (const uint4*)(xb + (size_t)q * NC);
            acc_row8(t, sav, row[lane]);
        } else {
            int anch = g_anchor[gid];
            int bx = (anch & 255) - 8, by = ((anch >> 8) & 255) - 8;
            int4 pj = g_pinv[gid];
            float4 T = g_T[(size_t)gid * 16 + (lane & 15)];
            float wc = T.x * saab[pj.x] + T.y * saab[pj.y] +
                       T.z * saab[pj.z] + T.w * saab[pj.w];
            unsigned mask = (((unsigned)anch) >> 16) &
                            __ballot_sync(0xffffffffu, wc > WEPS);
            while (mask) {
                int k = __ffs(mask) - 1;
                mask &= mask - 1;
                float w = __shfl_sync(0xffffffffu, wc, k);
                const uint4* row = (const uint4*)(xb +
                    ((by + (k >> 2)) * NW + bx + (k & 3)) * NC);
                acc_row8(t, w, row[lane]);
            }
        }

        float4 ca0 = car[lane * 2], ca1 = car[lane * 2 + 1];
        res[0] = fmaf(ca0.x, t[0], res[0]); res[1] = fmaf(ca0.y, t[1], res[1]);
        res[2] = fmaf(ca0.z, t[2], res[2]); res[3] = fmaf(ca0.w, t[3], res[3]);
        res[4] = fmaf(ca1.x, t[4], res[4]); res[5] = fmaf(ca1.y, t[5], res[5]);
        res[6] = fmaf(ca1.z, t[6], res[6]); res[7] = fmaf(ca1.w, t[7], res[7]);
    }

    // smem transpose: s[pixel][channel] -> NCHW stores with /4 folded in
    *(float4*)&s[wid][lane * 8]     = make_float4(res[0], res[1], res[2], res[3]);
    *(float4*)&s[wid][lane * 8 + 4] = make_float4(res[4], res[5], res[6], res[7]);
    __syncthreads();
    int pix = lane & 15, hl = lane >> 4;
#pragma unroll
    for (int it = 0; it < 8; it++) {
        int c = wid * 16 + hl * 8 + it;
        float v = s[pix][c];
        out[((size_t)(b * NC + c)) * NHW + q0 + pix] = v * 0.25f;
    }
}

// ---------------- launch ----------------
extern "C" void kernel_launch(void* const* d_in, const int* in_sizes, int n_in,
                              void* d_out, int out_size) {
    const float* x      = (const float*)d_in[0];
    const float* angles = (const float*)d_in[1];
    const float* w1     = (const float*)d_in[2];
    const float* bng    = (const float*)d_in[3];
    const float* bnb    = (const float*)d_in[4];
    const float* bnm    = (const float*)d_in[5];
    const float* bnv    = (const float*)d_in[6];
    const float* w2     = (const float*)d_in[7];
    const float* wsp    = (const float*)d_in[8];
    float* out = (float*)d_out;

    dim3 tb(32, 32);
    k_transpose<<<dim3(NHW / 32, NC / 64, NB), tb>>>(x);
    k_Amap<<<(NANG * NHW) / 256, 256>>>(angles);
    k_mean<<<NB * NGRP / 8, 256>>>();
    k_reduce<<<NANG * NB * NRED, 256>>>();
    k_chatt<<<NANG * NB, 256>>>(w1, bng, bnb, bnm, bnv, w2);
    k_avgmax<<<(NANG * NB * NHW / 2) / 8, 256>>>();
    k_conv<<<(NANG * NB * NHW) / 256, 256>>>(wsp);
    k_fused<<<NB * NHW / 16, 512>>>(out);
}

// round 17
// speedup vs baseline: 1.1117x; 1.0528x over previous
#include <cuda_runtime.h>
#include <cuda_fp16.h>
#include <math.h>

#define NB   8
#define NC   256
#define NH   128
#define NW   128
#define NHW  16384
#define NMID 64
#define NANG 4
#define GRPPIX 64
#define NGRP (NHW / GRPPIX)    // 256 pixel-groups per image
#define NRED 8                 // second-stage partials per (a,b)
#define WEPS 1e-5f

// ---------------- scratch (static __device__, no allocations) ----------------
__device__ __half g_xh[(size_t)NB * NHW * NC];     // 67 MB  x in NHWC fp16 (L2-resident)
__device__ float g_trig[2 * NANG];
__device__ float g_A4[NHW * 4];                    // per-pixel A weights, 4 angles packed
__device__ float g_mpart[(size_t)NANG * NB * NGRP * NC];
__device__ float g_mpart2[(size_t)NANG * NB * NRED * NC];
__device__ float g_ca[NANG * NB * NC];
__device__ float g_avg[(size_t)NANG * NB * NHW];
__device__ float g_maxm[(size_t)NANG * NB * NHW];
__device__ float g_sa[(size_t)NANG * NB * NHW];
// precomputed geometry (batch-invariant)
__device__ int4   g_gidx[NANG * NHW];              // fwd gather corner pixel idx (-1 = skip)
__device__ float4 g_gw[NANG * NHW];                // fwd gather corner weights
__device__ float4 g_T[(size_t)NANG * NHW * 16];    // fused: per-cell 4-corner tent weights
__device__ int4   g_pinv[NANG * NHW];              // fused: inverse-corner sa indices
__device__ int    g_anchor[NANG * NHW];            // diag: (bx+8)|(by+8)<<8|mask<<16 ; ident: p_inv idx

// ---------------- helpers ----------------
__device__ __forceinline__ float ncoord(int j) { return -1.0f + (float)j * (2.0f / 127.0f); }
__device__ __forceinline__ float ncoordf(float j) { return -1.0f + j * (2.0f / 127.0f); }
__device__ __forceinline__ float sigm(float v) { return 1.0f / (1.0f + expf(-v)); }

// Accumulate w * 8 fp16 channels (one uint4 row chunk) into fp32 acc[8].
__device__ __forceinline__ void acc_row8(float* acc, float w, const uint4 h) {
    const __half2* hp = (const __half2*)&h;
#pragma unroll
    for (int i = 0; i < 4; i++) {
        float2 f = __half22float2(hp[i]);
        acc[2 * i]     = fmaf(w, f.x, acc[2 * i]);
        acc[2 * i + 1] = fmaf(w, f.y, acc[2 * i + 1]);
    }
}

// ---------------- kernels ----------------

// Pure NCHW -> NHWC(fp16) transpose (64-channel tiles, half2 stores).
__global__ void k_transpose(const float* __restrict__ x) {
    __shared__ float s[64][33];
    int b = blockIdx.z, c0 = blockIdx.y * 64, p0 = blockIdx.x * 32;
    int tx = threadIdx.x, ty = threadIdx.y;
    s[ty][tx]      = x[((size_t)(b * NC + c0 + ty)) * NHW + p0 + tx];
    s[ty + 32][tx] = x[((size_t)(b * NC + c0 + 32 + ty)) * NHW + p0 + tx];
    __syncthreads();
    __half2 h2 = __floats2half2_rn(s[2 * tx][ty], s[2 * tx + 1][ty]);
    *(__half2*)(g_xh + ((size_t)b * NHW + p0 + ty) * NC + c0 + 2 * tx) = h2;
}

// A map + batch-invariant geometry precompute; one thread per (angle, pixel).
__global__ void k_Amap(const float* __restrict__ angles) {
    int id = blockIdx.x * 256 + threadIdx.x;
    int a = id >> 14, p = id & (NHW - 1);
    float ang = angles[a];
    float c_ = cosf(ang), s_ = sinf(ang);
    if (blockIdx.x == 0 && threadIdx.x < NANG) {
        float aa = angles[threadIdx.x];
        g_trig[2 * threadIdx.x]     = cosf(aa);
        g_trig[2 * threadIdx.x + 1] = sinf(aa);
    }
    int sy = p >> 7, sx = p & 127;

    // ---- A map (source-pixel weight accumulation), packed per-pixel float4 ----
    {
        float dx = (float)sx - 63.5f, dy = (float)sy - 63.5f;
        float pxf = c_ * dx + s_ * dy + 63.5f;
        float pyf = -s_ * dx + c_ * dy + 63.5f;
        int px0 = (int)floorf(pxf + 0.5f) - 2;
        int py0 = (int)floorf(pyf + 0.5f) - 2;
        float acc = 0.f;
        for (int py = py0; py < py0 + 5; py++) {
            for (int px = px0; px < px0 + 5; px++) {
                if ((unsigned)px < 128u && (unsigned)py < 128u) {
                    float X = ncoord(px), Y = ncoord(py);
                    float gx = c_ * X - s_ * Y, gy = s_ * X + c_ * Y;
                    float ix = (gx + 1.0f) * 63.5f, iy = (gy + 1.0f) * 63.5f;
                    float tx = 1.0f - fabsf(ix - (float)sx);
                    float ty = 1.0f - fabsf(iy - (float)sy);
                    if (tx > 0.f && ty > 0.f) acc += tx * ty;
                }
            }
        }
        g_A4[p * 4 + a] = acc * (1.0f / (float)NHW);
    }

    float X = ncoord(sx), Y = ncoord(sy);

    // ---- forward-gather corner geometry (for k_avgmax) ----
    {
        float gx = c_ * X - s_ * Y, gy = s_ * X + c_ * Y;
        float fix = (gx + 1.0f) * 63.5f, fiy = (gy + 1.0f) * 63.5f;
        float fx0 = floorf(fix), fy0 = floorf(fiy);
        float wx1 = fix - fx0, wx0 = 1.0f - wx1;
        float wy1 = fiy - fy0, wy0 = 1.0f - wy1;
        float cx[4] = {fx0, fx0 + 1.0f, fx0,        fx0 + 1.0f};
        float cy[4] = {fy0, fy0,        fy0 + 1.0f, fy0 + 1.0f};
        float cw[4] = {wx0 * wy0, wx1 * wy0, wx0 * wy1, wx1 * wy1};
        int gi[4]; float gw[4];
#pragma unroll
        for (int k = 0; k < 4; k++) {
            bool ok = (cx[k] >= 0.f && cx[k] <= 127.f && cy[k] >= 0.f &&
                       cy[k] <= 127.f && cw[k] > WEPS);
            gi[k] = ok ? ((int)cy[k] * NW + (int)cx[k]) : -1;
            gw[k] = cw[k];
        }
        g_gidx[id] = make_int4(gi[0], gi[1], gi[2], gi[3]);
        g_gw[id]   = make_float4(gw[0], gw[1], gw[2], gw[3]);
    }

    // ---- inverse-pass geometry (for k_fused) ----
    {
        float gx = c_ * X + s_ * Y, gy = -s_ * X + c_ * Y;   // inverse grid
        float ixv = (gx + 1.0f) * 63.5f, iyv = (gy + 1.0f) * 63.5f;

        if (fabsf(s_) < 1e-4f || fabsf(c_) < 1e-4f) {
            // identity (grid-preserving) angle: store only the inverse pixel index
            int pxi = (int)(ixv + 0.5f), pyi = (int)(iyv + 0.5f);
            g_anchor[id] = pyi * NW + pxi;
        } else {
            float x0 = floorf(ixv), y0 = floorf(iyv);
            float wx1 = ixv - x0, wx0 = 1.0f - wx1;
            float wy1 = iyv - y0, wy0 = 1.0f - wy1;

            float fx[4], fy[4], wj[4];
            int pj[4];
            float minfx = 1e9f, minfy = 1e9f;
#pragma unroll
            for (int j = 0; j < 4; j++) {
                float fpx = x0 + (float)(j & 1);
                float fpy = y0 + (float)(j >> 1);
                float wi = ((j & 1) ? wx1 : wx0) * ((j >> 1) ? wy1 : wy0);
                bool ok = (fpx >= 0.f && fpx <= 127.f && fpy >= 0.f && fpy <= 127.f &&
                           wi > WEPS);
                wj[j] = ok ? wi : 0.f;
                pj[j] = ok ? ((int)fpy * NW + (int)fpx) : 0;
                if (ok) {
                    float fgx = c_ * ncoordf(fpx) - s_ * ncoordf(fpy);
                    float fgy = s_ * ncoordf(fpx) + c_ * ncoordf(fpy);
                    fx[j] = (fgx + 1.0f) * 63.5f;
                    fy[j] = (fgy + 1.0f) * 63.5f;
                    minfx = fminf(minfx, fx[j]);
                    minfy = fminf(minfy, fy[j]);
                } else {
                    fx[j] = 1e9f; fy[j] = 1e9f;
                }
            }
            int bx = 0, by = 0;
            if (minfx < 500.f) {
                bx = (int)floorf(minfx);
                by = (int)floorf(minfy);
            }
            g_pinv[id] = make_int4(pj[0], pj[1], pj[2], pj[3]);
            float4* Trow = g_T + (size_t)id * 16;
            unsigned tmask = 0;
#pragma unroll
            for (int cell = 0; cell < 16; cell++) {
                int cxk = bx + (cell & 3), cyk = by + ((cell >> 2) & 3);
                float cellx = (float)cxk, celly = (float)cyk;
                float t[4];
                float tsum = 0.f;
#pragma unroll
                for (int j = 0; j < 4; j++) {
                    float tx = fmaxf(0.f, 1.0f - fabsf(fx[j] - cellx));
                    float ty = fmaxf(0.f, 1.0f - fabsf(fy[j] - celly));
                    t[j] = wj[j] * tx * ty;
                    tsum += t[j];
                }
                Trow[cell] = make_float4(t[0], t[1], t[2], t[3]);
                if ((unsigned)cxk < 128u && (unsigned)cyk < 128u && tsum > WEPS)
                    tmask |= 1u << cell;
            }
            g_anchor[id] = (bx + 8) | ((by + 8) << 8) | ((int)tmask << 16);
        }
    }
}

// Weighted means for all 4 angles in ONE pass over x (NHWC fp16).
// Warp per 64-pixel group; lane owns 8 channels -> NO cross-lane reduction.
__global__ void k_mean() {
    int w = blockIdx.x * 8 + (threadIdx.x >> 5);
    int lane = threadIdx.x & 31;
    int b = w >> 8;                  // NGRP = 256 groups per batch
    int grp = w & (NGRP - 1);
    const __half* xb = g_xh + ((size_t)b * NHW + grp * GRPPIX) * NC;
    const float4* A4 = (const float4*)g_A4 + grp * GRPPIX;
    float acc[4][8];
#pragma unroll
    for (int a = 0; a < 4; a++)
#pragma unroll
        for (int i = 0; i < 8; i++) acc[a][i] = 0.f;
#pragma unroll 4
    for (int p = 0; p < GRPPIX; p++) {
        uint4 row = ((const uint4*)(xb + (size_t)p * NC))[lane];
        float4 aw = A4[p];
        const __half2* hp = (const __half2*)&row;
        float f[8];
#pragma unroll
        for (int i = 0; i < 4; i++) {
            float2 v = __half22float2(hp[i]);
            f[2 * i] = v.x; f[2 * i + 1] = v.y;
        }
#pragma unroll
        for (int i = 0; i < 8; i++) {
            acc[0][i] = fmaf(aw.x, f[i], acc[0][i]);
            acc[1][i] = fmaf(aw.y, f[i], acc[1][i]);
            acc[2][i] = fmaf(aw.z, f[i], acc[2][i]);
            acc[3][i] = fmaf(aw.w, f[i], acc[3][i]);
        }
    }
#pragma unroll
    for (int a = 0; a < 4; a++)
#pragma unroll
        for (int i = 0; i < 8; i++)
            g_mpart[((size_t)((a * NB + b) * NGRP) + grp) * NC + lane * 8 + i] = acc[a][i];
}

// Stage-A reduction: 256 blocks; block (ab, part) reduces 32 group-partials.
__global__ void k_reduce() {
    int ab = blockIdx.x >> 3;
    int part = blockIdx.x & 7;
    int tid = threadIdx.x;
    const float* src = g_mpart + ((size_t)ab * NGRP + part * 32) * NC + tid;
    float s = 0.f;
#pragma unroll 8
    for (int g = 0; g < 32; g++) s += src[(size_t)g * NC];
    g_mpart2[((size_t)ab * NRED + part) * NC + tid] = s;
}

// Final 8-way reduction + channel attention MLP.
__global__ void k_chatt(const float* __restrict__ w1, const float* __restrict__ bng,
                        const float* __restrict__ bnb, const float* __restrict__ bnm,
                        const float* __restrict__ bnv, const float* __restrict__ w2) {
    __shared__ float sm[NC];
    __shared__ float sh[NMID];
    int ab = blockIdx.x;
    int tid = threadIdx.x;
    {
        const float* src = g_mpart2 + (size_t)ab * NRED * NC + tid;
        float ssum = 0.f;
#pragma unroll
        for (int g = 0; g < NRED; g++) ssum += src[(size_t)g * NC];
        sm[tid] = ssum;
    }
    __syncthreads();
    if (tid < NMID) {
        float hv = 0.f;
        const float* w1r = w1 + tid * NC;
        for (int c = 0; c < NC; c++) hv = fmaf(sm[c], w1r[c], hv);
        hv = (hv - bnm[tid]) * rsqrtf(bnv[tid] + 1e-5f) * bng[tid] + bnb[tid];
        sh[tid] = fmaxf(hv, 0.f);
    }
    __syncthreads();
    float cv = 0.f;
    const float* w2r = w2 + tid * NMID;
    for (int j = 0; j < NMID; j++) cv = fmaf(sh[j], w2r[j], cv);
    g_ca[ab * NC + tid] = sigm(cv);
}

// Channel-attended rotated stats; 2 adjacent pixels per warp (R13 proven form).
__global__ void k_avgmax() {
    int w2 = blockIdx.x * 8 + (threadIdx.x >> 5);
    int lane = threadIdx.x & 31;
    int a = w2 >> 16;
    int b = (w2 >> 13) & 7;
    int p = (w2 & 8191) * 2;
    const __half* xb = g_xh + (size_t)b * NHW * NC;
    int gid = a * NHW + p;
    int4 gi0 = g_gidx[gid], gi1 = g_gidx[gid + 1];
    float4 gw0 = g_gw[gid], gw1 = g_gw[gid + 1];
    float acc0[8], acc1[8];
#pragma unroll
    for (int i = 0; i < 8; i++) { acc0[i] = 0.f; acc1[i] = 0.f; }
    {
        int gia[4] = {gi0.x, gi0.y, gi0.z, gi0.w};
        float gwa[4] = {gw0.x, gw0.y, gw0.z, gw0.w};
#pragma unroll
        for (int k = 0; k < 4; k++)
            if (gia[k] >= 0)
                acc_row8(acc0, gwa[k], ((const uint4*)(xb + (size_t)gia[k] * NC))[lane]);
    }
    {
        int gia[4] = {gi1.x, gi1.y, gi1.z, gi1.w};
        float gwa[4] = {gw1.x, gw1.y, gw1.z, gw1.w};
#pragma unroll
        for (int k = 0; k < 4; k++)
            if (gia[k] >= 0)
                acc_row8(acc1, gwa[k], ((const uint4*)(xb + (size_t)gia[k] * NC))[lane]);
    }
    const float4* car = (const float4*)(g_ca + (size_t)(a * NB + b) * NC);
    float4 ca0 = car[lane * 2], ca1 = car[lane * 2 + 1];
    float cav[8] = {ca0.x, ca0.y, ca0.z, ca0.w, ca1.x, ca1.y, ca1.z, ca1.w};
    float sum0 = 0.f, mx0 = -1e30f, sum1 = 0.f, mx1 = -1e30f;
#pragma unroll
    for (int i = 0; i < 8; i++) {
        float u = cav[i] * acc0[i], v = cav[i] * acc1[i];
        sum0 += u; mx0 = fmaxf(mx0, u);
        sum1 += v; mx1 = fmaxf(mx1, v);
    }
#pragma unroll
    for (int o = 16; o; o >>= 1) {
        sum0 += __shfl_xor_sync(0xffffffffu, sum0, o);
        mx0 = fmaxf(mx0, __shfl_xor_sync(0xffffffffu, mx0, o));
        sum1 += __shfl_xor_sync(0xffffffffu, sum1, o);
        mx1 = fmaxf(mx1, __shfl_xor_sync(0xffffffffu, mx1, o));
    }
    if (lane == 0) {
        size_t base = (size_t)(a * NB + b) * NHW + p;
        g_avg[base]     = sum0 * (1.0f / (float)NC);
        g_avg[base + 1] = sum1 * (1.0f / (float)NC);
        g_maxm[base]     = mx0;
        g_maxm[base + 1] = mx1;
    }
}

__global__ void k_conv(const float* __restrict__ wsp) {
    __shared__ float sw[98];
    int tid = threadIdx.x;
    if (tid < 98) sw[tid] = wsp[tid];
    __syncthreads();
    int id = blockIdx.x * 256 + tid;
    int ab = id >> 14;
    int p = id & (NHW - 1);
    int py = p >> 7, px = p & 127;
    const float* av = g_avg + (size_t)ab * NHW;
    const float* mxp = g_maxm + (size_t)ab * NHW;
    float acc = 0.f;
#pragma unroll
    for (int ky = 0; ky < 7; ky++) {
        int yy = py + ky - 3;
        if ((unsigned)yy < 128u) {
#pragma unroll
            for (int kx = 0; kx < 7; kx++) {
                int xx = px + kx - 3;
                if ((unsigned)xx < 128u) {
                    int q = yy * NW + xx;
                    acc = fmaf(sw[ky * 7 + kx], av[q], acc);
                    acc = fmaf(sw[49 + ky * 7 + kx], mxp[q], acc);
                }
            }
        }
    }
    g_sa[id] = sigm(acc);
}

// Fused inverse pass, 1 warp / pixel, 256-thread blocks (8 pixels) at
// __launch_bounds__(256,5): 40 warps/SM (vs 32 before) to hide gather latency.
// Identity angles: precomputed inverse index in g_anchor. Diagonal angles:
// precomputed T matrices + 16-bit valid-mask walk.
__global__ void __launch_bounds__(256, 5) k_fused(float* __restrict__ out) {
    __shared__ float s[8][260];
    int b = blockIdx.x >> 11;            // 2048 8-pixel tiles per image
    int q0 = (blockIdx.x & 2047) * 8;
    int wid = threadIdx.x >> 5, lane = threadIdx.x & 31;
    int q = q0 + wid;
    const __half* xb = g_xh + (size_t)b * NHW * NC;
    float res[8];
#pragma unroll
    for (int i = 0; i < 8; i++) res[i] = 0.f;

#pragma unroll
    for (int a = 0; a < NANG; a++) {
        float c_ = g_trig[2 * a], s_ = g_trig[2 * a + 1];
        const float* saab = g_sa + (size_t)(a * NB + b) * NHW;
        const float4* car = (const float4*)(g_ca + (size_t)(a * NB + b) * NC);

        float t[8];
#pragma unroll
        for (int i = 0; i < 8; i++) t[i] = 0.f;

        int gid = a * NHW + q;
        if (fabsf(s_) < 1e-4f || fabsf(c_) < 1e-4f) {
            // grid-preserving rotation: anchor word IS the inverse pixel index
            int pinv = g_anchor[gid];
            float sav = saab[pinv];
            const uint4* row = (const uint4*)(xb + (size_t)q * NC);
            acc_row8(t, sav, row[lane]);
        } else {
            int anch = g_anchor[gid];
            int bx = (anch & 255) - 8, by = ((anch >> 8) & 255) - 8;
            int4 pj = g_pinv[gid];
            float4 T = g_T[(size_t)gid * 16 + (lane & 15)];
            float wc = T.x * saab[pj.x] + T.y * saab[pj.y] +
                       T.z * saab[pj.z] + T.w * saab[pj.w];
            unsigned mask = (((unsigned)anch) >> 16) &
                            __ballot_sync(0xffffffffu, wc > WEPS);
            while (mask) {
                int k = __ffs(mask) - 1;
                mask &= mask - 1;
                float w = __shfl_sync(0xffffffffu, wc, k);
                const uint4* row = (const uint4*)(xb +
                    ((by + (k >> 2)) * NW + bx + (k & 3)) * NC);
                acc_row8(t, w, row[lane]);
            }
        }

        float4 ca0 = car[lane * 2], ca1 = car[lane * 2 + 1];
        res[0] = fmaf(ca0.x, t[0], res[0]); res[1] = fmaf(ca0.y, t[1], res[1]);
        res[2] = fmaf(ca0.z, t[2], res[2]); res[3] = fmaf(ca0.w, t[3], res[3]);
        res[4] = fmaf(ca1.x, t[4], res[4]); res[5] = fmaf(ca1.y, t[5], res[5]);
        res[6] = fmaf(ca1.z, t[6], res[6]); res[7] = fmaf(ca1.w, t[7], res[7]);
    }

    // smem transpose: s[pixel][channel] -> NCHW stores with /4 folded in
    *(float4*)&s[wid][lane * 8]     = make_float4(res[0], res[1], res[2], res[3]);
    *(float4*)&s[wid][lane * 8 + 4] = make_float4(res[4], res[5], res[6], res[7]);
    __syncthreads();
    int pix = lane & 7, grp = lane >> 3;   // 4 channel-subgroups x 8 pixels
#pragma unroll
    for (int it = 0; it < 8; it++) {
        int c = wid * 32 + grp * 8 + it;
        float v = s[pix][c];
        out[((size_t)(b * NC + c)) * NHW + q0 + pix] = v * 0.25f;
    }
}

// ---------------- launch ----------------
extern "C" void kernel_launch(void* const* d_in, const int* in_sizes, int n_in,
                              void* d_out, int out_size) {
    const float* x      = (const float*)d_in[0];
    const float* angles = (const float*)d_in[1];
    const float* w1     = (const float*)d_in[2];
    const float* bng    = (const float*)d_in[3];
    const float* bnb    = (const float*)d_in[4];
    const float* bnm    = (const float*)d_in[5];
    const float* bnv    = (const float*)d_in[6];
    const float* w2     = (const float*)d_in[7];
    const float* wsp    = (const float*)d_in[8];
    float* out = (float*)d_out;

    dim3 tb(32, 32);
    k_transpose<<<dim3(NHW / 32, NC / 64, NB), tb>>>(x);
    k_Amap<<<(NANG * NHW) / 256, 256>>>(angles);
    k_mean<<<NB * NGRP / 8, 256>>>();
    k_reduce<<<NANG * NB * NRED, 256>>>();
    k_chatt<<<NANG * NB, 256>>>(w1, bng, bnb, bnm, bnv, w2);
    k_avgmax<<<(NANG * NB * NHW / 2) / 8, 256>>>();
    k_conv<<<(NANG * NB * NHW) / 256, 256>>>(wsp);
    k_fused<<<NB * NHW / 8, 256>>>(out);
}